// round 13
// baseline (speedup 1.0000x reference)
#include <cuda_runtime.h>
#include <cuda_fp16.h>

#define Bq 512
#define Tq 256
#define Fq 128
#define Hq 256
#define BTF (Bq*Tq*Fq)

typedef unsigned long long ull;

// ---------------- device scratch (no allocations allowed) ----------------
__device__ __align__(16) float  g_WdhT[Fq*Hq];        // [k in F][j in H]  fp32 (L2)
__device__ __align__(16) __half g_WhT_h[Hq*Fq];       // [k in H][j in F]  fp16 (smem src)
__device__ __align__(16) __half g_WfT_h[Fq*Fq];       // diag zeroed       fp16 (smem src)
__device__ __align__(16) __half g_WcT_h[2*Fq*Fq];     // [k in 2F][j in F] fp16 (smem src)
__device__ __align__(16) __half g_WihT_h[2*Fq*4*Hq];  // [k in 2F][j in 4H] fp16
__device__ __align__(16) __half g_WhhT_h[Hq*4*Hq];    // [k in H][j in 4H]  fp16
__device__ float g_wdx[Fq];
__device__ float g_bsum[4*Hq];
__device__ float g_D[Tq];

// ---------------- packed f32x2 helpers ----------------
__device__ __forceinline__ ull pack2(float x, float y) {
    ull r; asm("mov.b64 %0, {%1,%2};" : "=l"(r) : "f"(x), "f"(y)); return r;
}
__device__ __forceinline__ void unpack2(ull v, float& x, float& y) {
    asm("mov.b64 {%0,%1}, %2;" : "=f"(x), "=f"(y) : "l"(v));
}
__device__ __forceinline__ ull ffma2(ull a, ull b, ull c) {
    ull d; asm("fma.rn.f32x2 %0, %1, %2, %3;" : "=l"(d) : "l"(a), "l"(b), "l"(c)); return d;
}
__device__ __forceinline__ float sigm(float x) {
    return fmaf(0.5f, __tanhf(x * 0.5f), 0.5f);
}

struct __align__(8) H4 { __half2 a, b; };

// ---------------- prep: transpose weights, diag, bias sum, zero scalars ----------------
__global__ void prep_weights(const float* __restrict__ Wdh, const float* __restrict__ Wh,
                             const float* __restrict__ Wf,  const float* __restrict__ Wc,
                             const float* __restrict__ Wih, const float* __restrict__ Whh,
                             const float* __restrict__ Wdx, const float* __restrict__ bih,
                             const float* __restrict__ bhh, float* __restrict__ out, int out_size)
{
    int i0 = blockIdx.x * blockDim.x + threadIdx.x;
    int stride = gridDim.x * blockDim.x;

    for (int idx = i0; idx < 1024*256; idx += stride) {
        int j = idx >> 8, k = idx & 255;
        g_WihT_h[k*1024 + j] = __float2half(Wih[idx]);
        g_WhhT_h[k*1024 + j] = __float2half(Whh[idx]);
    }
    for (int idx = i0; idx < 256*128; idx += stride) {
        int j = idx >> 7, k = idx & 127;
        g_WdhT[k*256 + j] = Wdh[idx];
    }
    for (int idx = i0; idx < 128*256; idx += stride) {
        int j = idx >> 8, k = idx & 255;
        g_WhT_h[k*128 + j] = __float2half(Wh[idx]);
        g_WcT_h[k*128 + j] = __float2half(Wc[idx]);
    }
    for (int idx = i0; idx < 128*128; idx += stride) {
        int j = idx >> 7, k = idx & 127;
        g_WfT_h[k*128 + j] = (j == k) ? __float2half(0.f) : __float2half(Wf[idx]);
    }
    for (int idx = i0; idx < 128; idx += stride)  g_wdx[idx]  = Wdx[idx*128 + idx];
    for (int idx = i0; idx < 1024; idx += stride) g_bsum[idx] = bih[idx] + bhh[idx];
    for (int idx = i0; idx < 2; idx += stride)
        if (BTF + idx < out_size) out[BTF + idx] = 0.f;
}

// ---------------- per-timestep mask denominator ----------------
__global__ void mask_denom(const float* __restrict__ mask)
{
    int t = blockIdx.x;
    float s = 0.f;
    for (int i = threadIdx.x; i < Bq*Fq; i += blockDim.x) {
        int b = i >> 7, f = i & 127;
        s += mask[b*(Tq*Fq) + t*Fq + f];
    }
    for (int o = 16; o; o >>= 1) s += __shfl_down_sync(0xffffffffu, s, o);
    __shared__ float red[8];
    int lane = threadIdx.x & 31, wid = threadIdx.x >> 5;
    if (lane == 0) red[wid] = s;
    __syncthreads();
    if (threadIdx.x == 0) {
        float tt = 0.f;
        #pragma unroll
        for (int w = 0; w < 8; w++) tt += red[w];
        g_D[t] = tt;
    }
}

// fp16-weight GEMV with duplicated-f32x2 activations: act is [4][STR] of (v,v) ull.
// Per 2 k: 4 LDS.128 (act) + 2 LDG.64 (w) + cvt/pack + 16 ffma2.
template<int LEN, int STR>
__device__ __forceinline__ void gemv_acc_d(const __half* __restrict__ wbase,
                                           const ull* __restrict__ act,
                                           ull a01[4], ull a23[4])
{
    #pragma unroll 8
    for (int k2 = 0; k2 < LEN; k2 += 2) {
        ulonglong2 iv[4];
        #pragma unroll
        for (int b = 0; b < 4; b++)
            iv[b] = *(const ulonglong2*)(act + b*STR + k2);
        #pragma unroll
        for (int kk = 0; kk < 2; kk++) {
            H4 w = *(const H4*)(wbase + (k2 + kk)*1024);
            float2 w01 = __half22float2(w.a);
            float2 w23 = __half22float2(w.b);
            ull w01p = pack2(w01.x, w01.y);
            ull w23p = pack2(w23.x, w23.y);
            #pragma unroll
            for (int b = 0; b < 4; b++) {
                ull vp = kk ? iv[b].y : iv[b].x;
                a01[b] = ffma2(w01p, vp, a01[b]);
                a23[b] = ffma2(w23p, vp, a23[b]);
            }
        }
    }
}

// fp16 smem weight GEMV, f-pair outputs, duplicated-ull activations (LDS.64 per k).
__device__ __forceinline__ ull gemv_pair_d(const __half* __restrict__ w, int p,
                                           const ull* __restrict__ act, int len)
{
    ull a = 0ull;
    #pragma unroll 8
    for (int k = 0; k < len; k++) {
        float2 wf = __half22float2(((const __half2*)(w + k*Fq))[p]);
        a = ffma2(pack2(wf.x, wf.y), act[k], a);
    }
    return a;
}

// fp16 smem weight GEMV, f-pair outputs, scalar float activations.
__device__ __forceinline__ ull gemv_pair_s(const __half* __restrict__ w, int p,
                                           const float* __restrict__ act, int len)
{
    ull a = 0ull;
    #pragma unroll 8
    for (int k = 0; k < len; k++) {
        float2 wf = __half22float2(((const __half2*)(w + k*Fq))[p]);
        float v = act[k];
        a = ffma2(pack2(wf.x, wf.y), pack2(v, v), a);
    }
    return a;
}

#define DYN_SMEM_BYTES 184320   // 160KB weights + 8KB sh2 + 3*4KB dup buffers

// ---------------- main persistent kernel: 128 blocks x 512 threads x 4 rows ----------------
__global__ __launch_bounds__(512, 1)
void rits_persistent(const float* __restrict__ values, const float* __restrict__ mask,
                     const float* __restrict__ deltas,
                     const float* __restrict__ bdh, const float* __restrict__ bdx,
                     const float* __restrict__ bh,  const float* __restrict__ bf_,
                     const float* __restrict__ bc,  float* __restrict__ out, int out_size)
{
    extern __shared__ __align__(16) unsigned char dynsmem[];
    __half* s_WhT = (__half*)dynsmem;                          // [Hq][Fq]   64KB
    __half* s_WfT = (__half*)(dynsmem + 65536);                // [Fq][Fq]   32KB
    __half* s_WcT = (__half*)(dynsmem + 98304);                // [2Fq][Fq]  64KB
    ull* sh2  = (ull*)(dynsmem + 163840);                      // [4][Hq]     8KB dup
    ull* smk2 = (ull*)(dynsmem + 172032);                      // [4][Fq]     4KB dup
    ull* sgx2 = (ull*)(dynsmem + 176128);                      // [4][Fq]     4KB dup
    ull* scc2 = (ull*)(dynsmem + 180224);                      // [4][Fq]     4KB dup

    __shared__ __align__(16) float sh[4][Hq], sc[4][Hq];       // 8KB
    __shared__ __align__(16) float sx[4][Fq], sdx[4][Fq];      // 4KB (sdx: d in W1, x_c in W2)
    __shared__ __align__(16) float sgate[4][4*Hq];             // 16KB (A: cc part + bias)
    __shared__ __align__(16) float sgate2[4][4*Hq];            // 16KB (B: mask + Whh parts)
    __shared__ float redx[16], redm[16];

    const int tid = threadIdx.x;
    const int lane = tid & 31, wid = tid >> 5;
    const int rowBase = blockIdx.x * 4;
    const int bq = tid >> 7, fq = tid & 127;       // stage-1 element ownership
    const int jq = tid & 255, j0 = jq * 4;         // gemv column-quad ownership

    // per-thread invariant caches
    const float wdx_f = g_wdx[fq], bdx_f = bdx[fq];
    const float bdh_j = bdh[jq];                          // used by A (tid<256), j=tid
    const int pA = tid & 63, bA = (tid >> 6) & 3, f0A = 2*pA;
    const float2 bh2 = *(const float2*)&bh[f0A];
    const float2 bf2 = *(const float2*)&bf_[f0A];
    const float2 bc2 = *(const float2*)&bc[f0A];
    const float4 bsum4 = *(const float4*)&g_bsum[j0];

    // one-time smem weight fill: 160KB as uint4
    {
        const uint4* src = (const uint4*)g_WhT_h;
        uint4* dst = (uint4*)dynsmem;
        for (int i = tid; i < (Hq*Fq*2)/16; i += 512) dst[i] = src[i];
        const uint4* srcf = (const uint4*)g_WfT_h;
        uint4* dstf = (uint4*)(dynsmem + 65536);
        for (int i = tid; i < (Fq*Fq*2)/16; i += 512) dstf[i] = srcf[i];
        const uint4* srcc = (const uint4*)g_WcT_h;
        uint4* dstc = (uint4*)(dynsmem + 98304);
        for (int i = tid; i < (2*Fq*Fq*2)/16; i += 512) dstc[i] = srcc[i];
    }
    for (int i = tid; i < 4*Hq; i += 512) {
        (&sh[0][0])[i] = 0.f; (&sc[0][0])[i] = 0.f; sh2[i] = 0ull;
    }

    // prologue stage 1 for t = 0
    {
        int base0 = (rowBase + bq)*(Tq*Fq) + fq;
        float xv = values[base0], mv = mask[base0], dv = deltas[base0];
        sx[bq][fq] = xv; sdx[bq][fq] = dv;
        smk2[bq*Fq + fq] = pack2(mv, mv);
        float g = __expf(-fmaxf(dv * wdx_f + bdx_f, 0.f));
        sgx2[bq*Fq + fq] = pack2(g, g);
    }
    __syncthreads();

    float lx = 0.f, lm = 0.f;    // per-thread loss accumulators (A threads)

    for (int t = 0; t < Tq; t++) {
        // prefetch next-step inputs (whole step to cover DRAM latency)
        int tn = (t + 1 < Tq) ? t + 1 : t;
        int basen = (rowBase + bq)*(Tq*Fq) + tn*Fq + fq;
        float xv_n = values[basen], mv_n = mask[basen], dv_n = deltas[basen];

        ull a01[4], a23[4];
        #pragma unroll
        for (int b = 0; b < 4; b++) { a01[b] = 0ull; a23[b] = 0ull; }

        // ---- window 1: B streams Wih(mask); A runs stage 2 (gamma_h, decay h) ----
        if (tid >= 256) {
            gemv_acc_d<Fq, Fq>(&g_WihT_h[Fq*1024 + j0], smk2, a01, a23);
        } else {
            float a0 = 0.f, a1 = 0.f, a2 = 0.f, a3 = 0.f;
            #pragma unroll 8
            for (int k = 0; k < Fq; k++) {
                float w = g_WdhT[k*Hq + tid];
                a0 += w * sdx[0][k]; a1 += w * sdx[1][k];
                a2 += w * sdx[2][k]; a3 += w * sdx[3][k];
            }
            float h0 = sh[0][tid] * __expf(-fmaxf(a0 + bdh_j, 0.f));
            float h1 = sh[1][tid] * __expf(-fmaxf(a1 + bdh_j, 0.f));
            float h2 = sh[2][tid] * __expf(-fmaxf(a2 + bdh_j, 0.f));
            float h3 = sh[3][tid] * __expf(-fmaxf(a3 + bdh_j, 0.f));
            sh[0][tid] = h0; sh[1][tid] = h1; sh[2][tid] = h2; sh[3][tid] = h3;
            sh2[0*Hq + tid] = pack2(h0, h0);
            sh2[1*Hq + tid] = pack2(h1, h1);
            sh2[2*Hq + tid] = pack2(h2, h2);
            sh2[3*Hq + tid] = pack2(h3, h3);
        }
        __syncthreads();   // h/sh2 final until stage 7

        // ---- window 2: B streams Whh @ h; A runs stages 3-5 + Wih@c_c tail ----
        if (tid >= 256) {
            gemv_acc_d<Hq, Hq>(&g_WhhT_h[j0], sh2, a01, a23);
            #pragma unroll
            for (int b2 = 0; b2 < 4; b2++) {
                float g0, g1, g2, g3;
                unpack2(a01[b2], g0, g1);
                unpack2(a23[b2], g2, g3);
                float4 gv; gv.x = g0; gv.y = g1; gv.z = g2; gv.w = g3;
                *(float4*)&sgate2[b2][j0] = gv;
            }
        } else {
            const int p = pA, b = bA, f0 = f0A;
            float2 xp = *(const float2*)&sx[b][f0];
            float m0 = *(const float*)&smk2[b*Fq + f0];
            float m1 = *(const float*)&smk2[b*Fq + f0 + 1];

            // ---- stage 3: x_h = Wh @ h + bh; x_c -> sdx; loss1 ----
            float xh0, xh1, l1;
            {
                ull a = gemv_pair_d(s_WhT, p, &sh2[b*Hq], Hq);
                float s0, s1; unpack2(a, s0, s1);
                xh0 = s0 + bh2.x; xh1 = s1 + bh2.y;
                float2 xc;
                xc.x = m0*xp.x + (1.f - m0)*xh0;
                xc.y = m1*xp.y + (1.f - m1)*xh1;
                *(float2*)&sdx[b][f0] = xc;
                l1 = fabsf(xh0 - xp.x)*m0 + fabsf(xh1 - xp.y)*m1;
            }
            asm volatile("bar.sync 1, 256;" ::: "memory");

            // ---- stage 4: z_h = Wf_masked @ x_c + bf; loss2 ----
            float zh0, zh1, l2;
            {
                ull a = gemv_pair_s(s_WfT, p, &sdx[b][0], Fq);
                float s0, s1; unpack2(a, s0, s1);
                zh0 = s0 + bf2.x; zh1 = s1 + bf2.y;
                l2 = fabsf(zh0 - xp.x)*m0 + fabsf(zh1 - xp.y)*m1;
            }
            asm volatile("bar.sync 1, 256;" ::: "memory");

            // ---- stage 5: alpha, c_h, c_c (output, scc2); loss3 ----
            {
                ull a  = gemv_pair_d(s_WcT, p, &sgx2[b*Fq], Fq);
                ull a2 = gemv_pair_d(s_WcT + Fq*Fq, p, &smk2[b*Fq], Fq);
                float al0, al1, q0, q1;
                unpack2(a, al0, al1); unpack2(a2, q0, q1);
                al0 += q0 + bc2.x; al1 += q1 + bc2.y;
                float ch0 = al0*zh0 + (1.f - al0)*xh0;
                float ch1 = al1*zh1 + (1.f - al1)*xh1;
                float l3 = fabsf(ch0 - xp.x)*m0 + fabsf(ch1 - xp.y)*m1;
                float cc0 = m0*xp.x + (1.f - m0)*ch0;
                float cc1 = m1*xp.y + (1.f - m1)*ch1;
                ulonglong2 ccp; ccp.x = pack2(cc0, cc0); ccp.y = pack2(cc1, cc1);
                *(ulonglong2*)&scc2[b*Fq + f0] = ccp;
                float2 cco; cco.x = cc0; cco.y = cc1;
                *(float2*)&out[(rowBase + b)*(Tq*Fq) + t*Fq + f0] = cco;
                float inv = __fdividef(1.f, g_D[t] + 1e-9f);
                lx += (l1 + l2 + (float)(Tq - t)*l3) * inv;
                lm += l3 * inv;
            }
            asm volatile("bar.sync 1, 256;" ::: "memory");

            // ---- A tail: Wih @ c_c; write sgate = cc-part + bias ----
            gemv_acc_d<Fq, Fq>(&g_WihT_h[j0], scc2, a01, a23);
            #pragma unroll
            for (int b2 = 0; b2 < 4; b2++) {
                float g0, g1, g2, g3;
                unpack2(a01[b2], g0, g1);
                unpack2(a23[b2], g2, g3);
                float4 gv;
                gv.x = g0 + bsum4.x; gv.y = g1 + bsum4.y;
                gv.z = g2 + bsum4.z; gv.w = g3 + bsum4.w;
                *(float4*)&sgate[b2][j0] = gv;
            }
        }
        __syncthreads();

        // ---- phase E: stage 1(t+1) + stage 7 (LSTM update), then one barrier ----
        {
            // stage 1 for t+1 from prefetched registers
            sx[bq][fq] = xv_n; sdx[bq][fq] = dv_n;
            smk2[bq*Fq + fq] = pack2(mv_n, mv_n);
            float g = __expf(-fmaxf(dv_n * wdx_f + bdx_f, 0.f));
            sgx2[bq*Fq + fq] = pack2(g, g);

            // stage 7: gates = sgate + sgate2 (i, f, g, o)
            int u = tid & 255;
            int bp = (tid >> 8) * 2;
            #pragma unroll
            for (int bb = 0; bb < 2; bb++) {
                int b = bp + bb;
                float ig = sgate[b][u]        + sgate2[b][u];
                float fg = sgate[b][Hq + u]   + sgate2[b][Hq + u];
                float gg = sgate[b][2*Hq + u] + sgate2[b][2*Hq + u];
                float og = sgate[b][3*Hq + u] + sgate2[b][3*Hq + u];
                float si = sigm(ig);
                float sf = sigm(fg);
                float so = sigm(og);
                float tg = __tanhf(gg);
                float cn = sf*sc[b][u] + si*tg;
                sc[b][u] = cn;
                float hb = so * __tanhf(cn);
                sh[b][u] = hb;
                sh2[b*Hq + u] = pack2(hb, hb);
            }
        }
        __syncthreads();
    }

    // ---- final loss reduction across the block ----
    for (int o = 16; o; o >>= 1) {
        lx += __shfl_down_sync(0xffffffffu, lx, o);
        lm += __shfl_down_sync(0xffffffffu, lm, o);
    }
    if (lane == 0) { redx[wid] = lx; redm[wid] = lm; }
    __syncthreads();
    if (tid == 0 && BTF + 1 < out_size) {
        float tx = 0.f, tm = 0.f;
        #pragma unroll
        for (int w = 0; w < 16; w++) { tx += redx[w]; tm += redm[w]; }
        atomicAdd(&out[BTF],     tx * (1.f / (Tq * 3.0f)));
        atomicAdd(&out[BTF + 1], tm * (1.f / (float)Tq));
    }
}

// ---------------- launch ----------------
extern "C" void kernel_launch(void* const* d_in, const int* in_sizes, int n_in,
                              void* d_out, int out_size)
{
    const float* values = (const float*)d_in[0];
    const float* mask   = (const float*)d_in[1];
    const float* deltas = (const float*)d_in[2];
    const float* Wdh    = (const float*)d_in[3];
    const float* bdh    = (const float*)d_in[4];
    const float* Wdx    = (const float*)d_in[5];
    const float* bdx    = (const float*)d_in[6];
    const float* Wh     = (const float*)d_in[7];
    const float* bh     = (const float*)d_in[8];
    const float* Wf     = (const float*)d_in[9];
    const float* bf_    = (const float*)d_in[10];
    const float* Wc     = (const float*)d_in[11];
    const float* bc     = (const float*)d_in[12];
    const float* Wih    = (const float*)d_in[13];
    const float* Whh    = (const float*)d_in[14];
    const float* bih    = (const float*)d_in[15];
    const float* bhh    = (const float*)d_in[16];
    float* out = (float*)d_out;

    cudaFuncSetAttribute(rits_persistent,
                         cudaFuncAttributeMaxDynamicSharedMemorySize, DYN_SMEM_BYTES);

    prep_weights<<<256, 256>>>(Wdh, Wh, Wf, Wc, Wih, Whh, Wdx, bih, bhh, out, out_size);
    mask_denom<<<Tq, 256>>>(mask);
    rits_persistent<<<Bq/4, 512, DYN_SMEM_BYTES>>>(values, mask, deltas, bdh, bdx,
                                                   bh, bf_, bc, out, out_size);
}

// round 14
// speedup vs baseline: 1.1705x; 1.1705x over previous
#include <cuda_runtime.h>
#include <cuda_fp16.h>

#define Bq 512
#define Tq 256
#define Fq 128
#define Hq 256
#define BTF (Bq*Tq*Fq)

typedef unsigned long long ull;

// ---------------- device scratch (no allocations allowed) ----------------
__device__ __align__(16) float  g_WdhT[Fq*Hq];        // [k in F][j in H]  fp32 (L2)
__device__ __align__(16) __half g_WhT_h[Hq*Fq];       // [k in H][j in F]  fp16 (smem src)
__device__ __align__(16) __half g_WfT_h[Fq*Fq];       // diag zeroed       fp16 (smem src)
__device__ __align__(16) __half g_WcT_h[2*Fq*Fq];     // [k in 2F][j in F] fp16 (smem src)
__device__ __align__(16) __half g_WihT_h[2*Fq*4*Hq];  // [k in 2F][j in 4H] fp16
__device__ __align__(16) __half g_WhhT_h[Hq*4*Hq];    // [k in H][j in 4H]  fp16
__device__ float g_wdx[Fq];
__device__ float g_bsum[4*Hq];
__device__ float g_D[Tq];

// ---------------- packed f32x2 helpers ----------------
__device__ __forceinline__ ull pack2(float x, float y) {
    ull r; asm("mov.b64 %0, {%1,%2};" : "=l"(r) : "f"(x), "f"(y)); return r;
}
__device__ __forceinline__ void unpack2(ull v, float& x, float& y) {
    asm("mov.b64 {%0,%1}, %2;" : "=f"(x), "=f"(y) : "l"(v));
}
__device__ __forceinline__ ull ffma2(ull a, ull b, ull c) {
    ull d; asm("fma.rn.f32x2 %0, %1, %2, %3;" : "=l"(d) : "l"(a), "l"(b), "l"(c)); return d;
}
__device__ __forceinline__ float sigm(float x) {
    return fmaf(0.5f, __tanhf(x * 0.5f), 0.5f);
}

struct __align__(8) H4 { __half2 a, b; };

// ---------------- prep: transpose weights, diag, bias sum, zero scalars ----------------
__global__ void prep_weights(const float* __restrict__ Wdh, const float* __restrict__ Wh,
                             const float* __restrict__ Wf,  const float* __restrict__ Wc,
                             const float* __restrict__ Wih, const float* __restrict__ Whh,
                             const float* __restrict__ Wdx, const float* __restrict__ bih,
                             const float* __restrict__ bhh, float* __restrict__ out, int out_size)
{
    int i0 = blockIdx.x * blockDim.x + threadIdx.x;
    int stride = gridDim.x * blockDim.x;

    for (int idx = i0; idx < 1024*256; idx += stride) {
        int j = idx >> 8, k = idx & 255;
        g_WihT_h[k*1024 + j] = __float2half(Wih[idx]);
        g_WhhT_h[k*1024 + j] = __float2half(Whh[idx]);
    }
    for (int idx = i0; idx < 256*128; idx += stride) {
        int j = idx >> 7, k = idx & 127;
        g_WdhT[k*256 + j] = Wdh[idx];
    }
    for (int idx = i0; idx < 128*256; idx += stride) {
        int j = idx >> 8, k = idx & 255;
        g_WhT_h[k*128 + j] = __float2half(Wh[idx]);
        g_WcT_h[k*128 + j] = __float2half(Wc[idx]);
    }
    for (int idx = i0; idx < 128*128; idx += stride) {
        int j = idx >> 7, k = idx & 127;
        g_WfT_h[k*128 + j] = (j == k) ? __float2half(0.f) : __float2half(Wf[idx]);
    }
    for (int idx = i0; idx < 128; idx += stride)  g_wdx[idx]  = Wdx[idx*128 + idx];
    for (int idx = i0; idx < 1024; idx += stride) g_bsum[idx] = bih[idx] + bhh[idx];
    for (int idx = i0; idx < 2; idx += stride)
        if (BTF + idx < out_size) out[BTF + idx] = 0.f;
}

// ---------------- per-timestep mask denominator ----------------
__global__ void mask_denom(const float* __restrict__ mask)
{
    int t = blockIdx.x;
    float s = 0.f;
    for (int i = threadIdx.x; i < Bq*Fq; i += blockDim.x) {
        int b = i >> 7, f = i & 127;
        s += mask[b*(Tq*Fq) + t*Fq + f];
    }
    for (int o = 16; o; o >>= 1) s += __shfl_down_sync(0xffffffffu, s, o);
    __shared__ float red[8];
    int lane = threadIdx.x & 31, wid = threadIdx.x >> 5;
    if (lane == 0) red[wid] = s;
    __syncthreads();
    if (threadIdx.x == 0) {
        float tt = 0.f;
        #pragma unroll
        for (int w = 0; w < 8; w++) tt += red[w];
        g_D[t] = tt;
    }
}

// fp16-weight GEMV accumulator (R11-proven): act [4][STR] float smem, wbase ->
// column-quad j0 of a [*][1024] fp16 transposed matrix. float4 act loads,
// register packs (ALU dual-issues against FMA), unroll 8 for L2 latency cover.
template<int LEN, int STR>
__device__ __forceinline__ void gemv_acc_h(const __half* __restrict__ wbase,
                                           const float* __restrict__ act,
                                           ull a01[4], ull a23[4])
{
    #pragma unroll 8
    for (int k4 = 0; k4 < LEN; k4 += 4) {
        float4 iv[4];
        #pragma unroll
        for (int b = 0; b < 4; b++)
            iv[b] = *(const float4*)(act + b*STR + k4);
        #pragma unroll
        for (int kk = 0; kk < 4; kk++) {
            H4 w = *(const H4*)(wbase + (k4 + kk)*1024);
            float2 w01 = __half22float2(w.a);
            float2 w23 = __half22float2(w.b);
            ull w01p = pack2(w01.x, w01.y);
            ull w23p = pack2(w23.x, w23.y);
            #pragma unroll
            for (int b = 0; b < 4; b++) {
                float v = ((const float*)&iv[b])[kk];
                ull vp = pack2(v, v);
                a01[b] = ffma2(w01p, vp, a01[b]);
                a23[b] = ffma2(w23p, vp, a23[b]);
            }
        }
    }
}

// fp16 smem weight GEMV, f-pair outputs, scalar float activations (R11-proven).
__device__ __forceinline__ ull gemv_pair_h(const __half* __restrict__ w, int p,
                                           const float* __restrict__ act, int len)
{
    ull a = 0ull;
    #pragma unroll 8
    for (int k = 0; k < len; k++) {
        float2 wf = __half22float2(((const __half2*)(w + k*Fq))[p]);
        float v = act[k];
        a = ffma2(pack2(wf.x, wf.y), pack2(v, v), a);
    }
    return a;
}

#define DYN_SMEM_BYTES ((Hq*Fq + Fq*Fq + 2*Fq*Fq) * 2)   // 64KB + 32KB + 64KB = 160KB

// ---------------- main persistent kernel: 128 blocks x 512 threads x 4 rows ----------------
__global__ __launch_bounds__(512, 1)
void rits_persistent(const float* __restrict__ values, const float* __restrict__ mask,
                     const float* __restrict__ deltas,
                     const float* __restrict__ bdh, const float* __restrict__ bdx,
                     const float* __restrict__ bh,  const float* __restrict__ bf_,
                     const float* __restrict__ bc,  float* __restrict__ out, int out_size)
{
    // dynamic smem: fp16 Wh (64KB) + Wf (32KB) + Wc (64KB)
    extern __shared__ __align__(16) unsigned char dynsmem[];
    __half* s_WhT = (__half*)dynsmem;                          // [Hq][Fq]
    __half* s_WfT = (__half*)(dynsmem + Hq*Fq*2);              // [Fq][Fq]
    __half* s_WcT = (__half*)(dynsmem + Hq*Fq*2 + Fq*Fq*2);    // [2Fq][Fq]

    __shared__ __align__(16) float sh[4][Hq], sc[4][Hq];
    __shared__ __align__(16) float sx[4][Fq], smk[4][Fq], sd[4][Fq];
    __shared__ __align__(16) float sgx[4][Fq], sxc[4][Fq];
    __shared__ __align__(16) float sgate[4][4*Hq];             // A: cc-part + bias
    __shared__ __align__(16) float sgate2[4][4*Hq];            // B: mask + Whh parts
    __shared__ float redx[16], redm[16];

    float (*scc)[Fq] = sxc;   // alias: sxc dead after stage 4, scc written in stage 5

    const int tid = threadIdx.x;
    const int lane = tid & 31, wid = tid >> 5;
    const int rowBase = blockIdx.x * 4;
    const int bq = tid >> 7, fq = tid & 127;       // stage-1 element ownership
    const int jq = tid & 255, j0 = jq * 4;         // gemv column-quad ownership

    // hoisted per-thread invariants
    const float wdx_f = g_wdx[fq], bdx_f = bdx[fq];
    const float bdh_j = bdh[jq];
    const int pA = tid & 63, bA = (tid >> 6) & 3, f0A = 2*pA;
    const float2 bh2 = *(const float2*)&bh[f0A];
    const float2 bf2 = *(const float2*)&bf_[f0A];
    const float2 bc2 = *(const float2*)&bc[f0A];
    const float4 bsum4 = *(const float4*)&g_bsum[j0];

    // one-time smem weight fill (amortized over 256 steps): 160KB as uint4
    {
        const uint4* src = (const uint4*)g_WhT_h;
        uint4* dst = (uint4*)dynsmem;
        for (int i = tid; i < (Hq*Fq*2)/16; i += 512) dst[i] = src[i];
        const uint4* srcf = (const uint4*)g_WfT_h;
        uint4* dstf = (uint4*)(dynsmem + Hq*Fq*2);
        for (int i = tid; i < (Fq*Fq*2)/16; i += 512) dstf[i] = srcf[i];
        const uint4* srcc = (const uint4*)g_WcT_h;
        uint4* dstc = (uint4*)(dynsmem + Hq*Fq*2 + Fq*Fq*2);
        for (int i = tid; i < (2*Fq*Fq*2)/16; i += 512) dstc[i] = srcc[i];
    }
    for (int i = tid; i < 4*Hq; i += 512) { (&sh[0][0])[i] = 0.f; (&sc[0][0])[i] = 0.f; }

    // prologue: stage 1 for t = 0
    {
        int base0 = (rowBase + bq)*(Tq*Fq) + fq;
        float xv = values[base0], mv = mask[base0], dv = deltas[base0];
        sx[bq][fq] = xv; smk[bq][fq] = mv; sd[bq][fq] = dv;
        sgx[bq][fq] = __expf(-fmaxf(dv * wdx_f + bdx_f, 0.f));
    }
    __syncthreads();

    float lx = 0.f, lm = 0.f;    // per-thread loss accumulators (A threads)

    for (int t = 0; t < Tq; t++) {
        // prefetch next-step inputs (registers; consumed at the bottom of the step)
        int tn = (t + 1 < Tq) ? t + 1 : t;
        int basen = (rowBase + bq)*(Tq*Fq) + tn*Fq + fq;
        float xv_n = values[basen], mv_n = mask[basen], dv_n = deltas[basen];

        ull a01[4], a23[4];
        #pragma unroll
        for (int b = 0; b < 4; b++) { a01[b] = 0ull; a23[b] = 0ull; }

        // ---- window 1: B streams Wih(mask); A runs stage 2 (gamma_h, decay h) ----
        if (tid >= 256) {
            gemv_acc_h<Fq, Fq>(&g_WihT_h[Fq*1024 + j0], &smk[0][0], a01, a23);
        } else {
            float a0 = 0.f, a1 = 0.f, a2 = 0.f, a3 = 0.f;
            #pragma unroll 8
            for (int k = 0; k < Fq; k++) {
                float w = g_WdhT[k*Hq + tid];
                a0 += w * sd[0][k]; a1 += w * sd[1][k];
                a2 += w * sd[2][k]; a3 += w * sd[3][k];
            }
            sh[0][tid] *= __expf(-fmaxf(a0 + bdh_j, 0.f));
            sh[1][tid] *= __expf(-fmaxf(a1 + bdh_j, 0.f));
            sh[2][tid] *= __expf(-fmaxf(a2 + bdh_j, 0.f));
            sh[3][tid] *= __expf(-fmaxf(a3 + bdh_j, 0.f));
        }
        __syncthreads();   // h now final until stage 7

        // ---- window 2: B streams Whh @ h -> sgate2; A: stages 3-5 + Wih@c_c -> sgate ----
        if (tid >= 256) {
            gemv_acc_h<Hq, Hq>(&g_WhhT_h[j0], &sh[0][0], a01, a23);
            #pragma unroll
            for (int b2 = 0; b2 < 4; b2++) {
                float g0, g1, g2, g3;
                unpack2(a01[b2], g0, g1);
                unpack2(a23[b2], g2, g3);
                float4 gv; gv.x = g0; gv.y = g1; gv.z = g2; gv.w = g3;
                *(float4*)&sgate2[b2][j0] = gv;
            }
        } else {
            const int p = pA, b = bA, f0 = f0A;
            float2 xp = *(const float2*)&sx[b][f0];
            float2 mp = *(const float2*)&smk[b][f0];

            // ---- stage 3: x_h = Wh @ h + bh; x_c; loss1 (fp16 SMEM) ----
            float xh0, xh1, l1;
            {
                ull a = gemv_pair_h(s_WhT, p, &sh[b][0], Hq);
                float s0, s1; unpack2(a, s0, s1);
                xh0 = s0 + bh2.x; xh1 = s1 + bh2.y;
                float2 xc;
                xc.x = mp.x*xp.x + (1.f - mp.x)*xh0;
                xc.y = mp.y*xp.y + (1.f - mp.y)*xh1;
                *(float2*)&sxc[b][f0] = xc;
                l1 = fabsf(xh0 - xp.x)*mp.x + fabsf(xh1 - xp.y)*mp.y;
            }
            asm volatile("bar.sync 1, 256;" ::: "memory");

            // ---- stage 4: z_h = Wf_masked @ x_c + bf; loss2 (fp16 SMEM) ----
            float zh0, zh1, l2;
            {
                ull a = gemv_pair_h(s_WfT, p, &sxc[b][0], Fq);
                float s0, s1; unpack2(a, s0, s1);
                zh0 = s0 + bf2.x; zh1 = s1 + bf2.y;
                l2 = fabsf(zh0 - xp.x)*mp.x + fabsf(zh1 - xp.y)*mp.y;
            }
            asm volatile("bar.sync 1, 256;" ::: "memory");

            // ---- stage 5: alpha, c_h, c_c (output); loss3 (fp16 SMEM) ----
            {
                ull a  = gemv_pair_h(s_WcT, p, &sgx[b][0], Fq);
                ull a2 = gemv_pair_h(s_WcT + Fq*Fq, p, &smk[b][0], Fq);
                float al0, al1, q0, q1;
                unpack2(a, al0, al1); unpack2(a2, q0, q1);
                al0 += q0 + bc2.x; al1 += q1 + bc2.y;
                float ch0 = al0*zh0 + (1.f - al0)*xh0;
                float ch1 = al1*zh1 + (1.f - al1)*xh1;
                float l3 = fabsf(ch0 - xp.x)*mp.x + fabsf(ch1 - xp.y)*mp.y;
                float2 cc;
                cc.x = mp.x*xp.x + (1.f - mp.x)*ch0;
                cc.y = mp.y*xp.y + (1.f - mp.y)*ch1;
                *(float2*)&scc[b][f0] = cc;
                *(float2*)&out[(rowBase + b)*(Tq*Fq) + t*Fq + f0] = cc;
                float inv = __fdividef(1.f, g_D[t] + 1e-9f);
                lx += (l1 + l2 + (float)(Tq - t)*l3) * inv;
                lm += l3 * inv;
            }
            asm volatile("bar.sync 1, 256;" ::: "memory");

            // ---- A tail: Wih @ c_c; sgate = cc-part + (bih + bhh) ----
            gemv_acc_h<Fq, Fq>(&g_WihT_h[j0], &scc[0][0], a01, a23);
            #pragma unroll
            for (int b2 = 0; b2 < 4; b2++) {
                float g0, g1, g2, g3;
                unpack2(a01[b2], g0, g1);
                unpack2(a23[b2], g2, g3);
                float4 gv;
                gv.x = g0 + bsum4.x; gv.y = g1 + bsum4.y;
                gv.z = g2 + bsum4.z; gv.w = g3 + bsum4.w;
                *(float4*)&sgate[b2][j0] = gv;
            }
        }
        __syncthreads();

        // ---- phase E: stage 1(t+1) from prefetch + stage 7 (LSTM), one barrier ----
        {
            sx[bq][fq] = xv_n; smk[bq][fq] = mv_n; sd[bq][fq] = dv_n;
            sgx[bq][fq] = __expf(-fmaxf(dv_n * wdx_f + bdx_f, 0.f));

            int u = tid & 255;
            int bp = (tid >> 8) * 2;
            #pragma unroll
            for (int bb = 0; bb < 2; bb++) {
                int b = bp + bb;
                float ig = sgate[b][u]        + sgate2[b][u];
                float fg = sgate[b][Hq + u]   + sgate2[b][Hq + u];
                float gg = sgate[b][2*Hq + u] + sgate2[b][2*Hq + u];
                float og = sgate[b][3*Hq + u] + sgate2[b][3*Hq + u];
                float si = sigm(ig);
                float sf = sigm(fg);
                float so = sigm(og);
                float tg = __tanhf(gg);
                float cn = sf*sc[b][u] + si*tg;
                sc[b][u] = cn;
                sh[b][u] = so * __tanhf(cn);
            }
        }
        __syncthreads();
    }

    // ---- final loss reduction across the block ----
    for (int o = 16; o; o >>= 1) {
        lx += __shfl_down_sync(0xffffffffu, lx, o);
        lm += __shfl_down_sync(0xffffffffu, lm, o);
    }
    if (lane == 0) { redx[wid] = lx; redm[wid] = lm; }
    __syncthreads();
    if (tid == 0 && BTF + 1 < out_size) {
        float tx = 0.f, tm = 0.f;
        #pragma unroll
        for (int w = 0; w < 16; w++) { tx += redx[w]; tm += redm[w]; }
        atomicAdd(&out[BTF],     tx * (1.f / (Tq * 3.0f)));
        atomicAdd(&out[BTF + 1], tm * (1.f / (float)Tq));
    }
}

// ---------------- launch ----------------
extern "C" void kernel_launch(void* const* d_in, const int* in_sizes, int n_in,
                              void* d_out, int out_size)
{
    const float* values = (const float*)d_in[0];
    const float* mask   = (const float*)d_in[1];
    const float* deltas = (const float*)d_in[2];
    const float* Wdh    = (const float*)d_in[3];
    const float* bdh    = (const float*)d_in[4];
    const float* Wdx    = (const float*)d_in[5];
    const float* bdx    = (const float*)d_in[6];
    const float* Wh     = (const float*)d_in[7];
    const float* bh     = (const float*)d_in[8];
    const float* Wf     = (const float*)d_in[9];
    const float* bf_    = (const float*)d_in[10];
    const float* Wc     = (const float*)d_in[11];
    const float* bc     = (const float*)d_in[12];
    const float* Wih    = (const float*)d_in[13];
    const float* Whh    = (const float*)d_in[14];
    const float* bih    = (const float*)d_in[15];
    const float* bhh    = (const float*)d_in[16];
    float* out = (float*)d_out;

    cudaFuncSetAttribute(rits_persistent,
                         cudaFuncAttributeMaxDynamicSharedMemorySize, DYN_SMEM_BYTES);

    prep_weights<<<256, 256>>>(Wdh, Wh, Wf, Wc, Wih, Whh, Wdx, bih, bhh, out, out_size);
    mask_denom<<<Tq, 256>>>(mask);
    rits_persistent<<<Bq/4, 512, DYN_SMEM_BYTES>>>(values, mask, deltas, bdh, bdx,
                                                   bh, bf_, bc, out, out_size);
}